// round 4
// baseline (speedup 1.0000x reference)
#include <cuda_runtime.h>
#include <cuda_pipeline.h>
#include <cstdint>
#include <cstddef>

#define BB   32
#define NAA  32768
#define CC   81
#define NGG  24
#define SENT 0xFFFFFFFFu
#define NBIN 16384
#define TILE 256
#define NTILES ((BB*NAA)/TILE)      // 4096
#define TILE_F4 ((TILE*CC)/4)       // 5184
#define CAP  6144
#define MTH  1024                   // k_main threads (4 lanes per row)

// ---------------- scratch ------------------------------------------------------
__device__ float              g_ioumax[BB*NAA];
__device__ unsigned char      g_gtidx[BB*NAA];
__device__ unsigned long long g_bestkey[BB*NGG];
__device__ unsigned           g_negbits[BB*NAA];
__device__ unsigned           g_hcnt[BB*NBIN];
__device__ float              g_hsum[BB*NBIN];
__device__ float              g_numpos[BB], g_posce[BB], g_regsum[BB];
__device__ float              g_topk[2*BB];
__device__ int                g_K[2*BB];
__device__ int                g_ctr;

__device__ __forceinline__ unsigned redux_max(unsigned v){
    unsigned r; asm("redux.sync.max.u32 %0, %1, 0xffffffff;" : "=r"(r) : "r"(v)); return r;
}

// ---------------- init ---------------------------------------------------------
__global__ void k_init(){
    int i = blockIdx.x*256 + threadIdx.x;
    for (int j=i; j<BB*NBIN; j+=gridDim.x*256){ g_hcnt[j]=0u; g_hsum[j]=0.f; }
    if (i < BB*NGG) g_bestkey[i]=0ull;
    if (i < BB){ g_numpos[i]=0.f; g_posce[i]=0.f; g_regsum[i]=0.f; }
    if (i==0) g_ctr = 0;
}

// ---------------- K1: IoU matching (4 anchors/thread, REDUX per-GT) ------------
__global__ void __launch_bounds__(256) k_iou(const float* __restrict__ anchors,
                                             const float* __restrict__ gtb){
    __shared__ float gx0[NGG],gy0[NGG],gx1[NGG],gy1[NGG],garea[NGG];
    __shared__ unsigned long long skey[NGG];
    int b=blockIdx.y, t=threadIdx.x;
    if (t<NGG){
        float4 g=((const float4*)gtb)[b*NGG+t];
        float x0=g.x-0.5f*g.z, y0=g.y-0.5f*g.w, x1=g.x+0.5f*g.z, y1=g.y+0.5f*g.w;
        gx0[t]=x0; gy0[t]=y0; gx1[t]=x1; gy1[t]=y1; garea[t]=(x1-x0)*(y1-y0);
        skey[t]=0ull;
    }
    __syncthreads();
    int abase = blockIdx.x*1024 + t;
    float ax0[4],ay0[4],ax1[4],ay1[4],areaA[4];
    #pragma unroll
    for (int k=0;k<4;++k){
        float4 an=((const float4*)anchors)[abase+k*256];
        ax0[k]=an.x-0.5f*an.z; ay0[k]=an.y-0.5f*an.w;
        ax1[k]=an.x+0.5f*an.z; ay1[k]=an.y+0.5f*an.w;
        areaA[k]=(ax1[k]-ax0[k])*(ay1[k]-ay0[k]);
    }
    float best[4]={-1.f,-1.f,-1.f,-1.f}; int bg[4]={0,0,0,0};

    for (int g=0; g<NGG; ++g){
        float bi=-1.f; int bk=0;
        #pragma unroll
        for (int k=0;k<4;++k){
            float lx=fmaxf(ax0[k],gx0[g]), ly=fmaxf(ay0[k],gy0[g]);
            float rx=fminf(ax1[k],gx1[g]), ry=fminf(ay1[k],gy1[g]);
            float w=fmaxf(rx-lx,0.f), h=fmaxf(ry-ly,0.f);
            float inter=w*h;
            float uni=fmaxf(areaA[k]+garea[g]-inter, 1e-12f);
            float iou=inter/uni;
            if (iou>best[k]){best[k]=iou; bg[k]=g;}
            if (iou>bi){bi=iou; bk=k;}
        }
        unsigned mb=__float_as_uint(bi);
        unsigned M=redux_max(mb);
        unsigned rk=(mb==M)? (unsigned)(((3-bk)<<5)|(31-(t&31)))+1u : 0u;
        unsigned R=redux_max(rk);
        if ((t&31)==0){
            int wl=31-(int)((R-1u)&31u), wk=3-(int)((R-1u)>>5);
            unsigned a=(unsigned)(blockIdx.x*1024 + (t&~31) + wl + wk*256);
            atomicMax(&skey[g], ((unsigned long long)M<<32) | (0xFFFFFFFFu - a));
        }
    }
    #pragma unroll
    for (int k=0;k<4;++k){
        g_ioumax[b*NAA+abase+k*256]=best[k];
        g_gtidx[b*NAA+abase+k*256]=(unsigned char)bg[k];
    }
    __syncthreads();
    if (t<NGG) atomicMax(&g_bestkey[b*NGG+t], skey[t]);
}

// ---------------- K1b: mark forced positives (iou := 2.0) ----------------------
__global__ void k_force(){
    int i = threadIdx.x;
    if (i < BB*NGG){
        unsigned a = 0xFFFFFFFFu - (unsigned)(g_bestkey[i] & 0xFFFFFFFFull);
        int b = i / NGG;
        g_ioumax[(size_t)b*NAA + a] = 2.0f;
    }
}

// ---------------- K2: CE + classify + reg; 4 lanes per row ---------------------
__global__ void __launch_bounds__(MTH) k_main(const float* __restrict__ cls,
                                              const float* __restrict__ box,
                                              const float* __restrict__ anchors,
                                              const float* __restrict__ gtb,
                                              const int*   __restrict__ gtl){
    extern __shared__ float sbuf[];
    const int t = threadIdx.x;
    float* bufs[2] = { sbuf, sbuf + TILE*CC };
    __shared__ int s_tile;

    if (t==0) s_tile = atomicAdd(&g_ctr, 1);
    __syncthreads();
    int cur = s_tile;
    if (cur >= NTILES) return;
    {   // prologue load
        const float4* src=(const float4*)(cls + (size_t)cur*TILE*CC);
        float4* dst=(float4*)bufs[0];
        for (int i=t;i<TILE_F4;i+=MTH) __pipeline_memcpy_async(dst+i, src+i, 16);
        __pipeline_commit();
    }
    int idx = 0;
    const int rloc = t >> 2;     // row within tile
    const int j    = t & 3;      // lane within 4-lane group
    for(;;){
        __syncthreads();
        if (t==0) s_tile = atomicAdd(&g_ctr, 1);
        __syncthreads();
        int nxt = s_tile;
        if (nxt < NTILES){
            const float4* src=(const float4*)(cls + (size_t)nxt*TILE*CC);
            float4* dst=(float4*)bufs[idx^1];
            for (int i=t;i<TILE_F4;i+=MTH) __pipeline_memcpy_async(dst+i, src+i, 16);
            __pipeline_commit();
            __pipeline_wait_prior(1);
        } else {
            __pipeline_wait_prior(0);
        }
        __syncthreads();                   // current tile fully staged

        const float* r = bufs[idx] + rloc*CC;
        // lane j sums exp over classes j, j+4, ... (odd row length => benign banks)
        float s0=0.f, s1=0.f;
        #pragma unroll
        for (int c=0; c+4<81; c+=8){       // pairs: c+j and c+4+j
            s0 += __expf(r[c+j]);
            s1 += __expf(r[c+4+j]);
        }
        if (j==0) s0 += __expf(r[80]);     // c=80 leftover (80%4==0)
        float s = s0 + s1;
        s += __shfl_xor_sync(0xFFFFFFFFu, s, 1);
        s += __shfl_xor_sync(0xFFFFFFFFu, s, 2);

        float l_np=0.f, l_ce=0.f, l_rg=0.f;
        if (j==0){
            int row = cur*TILE + rloc;
            int b   = row >> 15;
            int a   = row & (NAA-1);
            float lse = __logf(s);
            float io  = g_ioumax[row];
            int   gi  = (int)g_gtidx[row];
            bool pos = io >= 0.5f;             // forced positives carry io=2.0
            bool ign = (!pos) && (io > 0.4f);
            if (pos){
                int tgt = gtl[b*NGG + gi];
                float ce = fmaxf(lse - r[tgt], 0.f);
                l_np = 1.f; l_ce = ce;
                float4 an = ((const float4*)anchors)[a];
                float4 g  = ((const float4*)gtb)[b*NGG + gi];
                float tx = (g.x - an.x) / an.z / 0.1f;
                float ty = (g.y - an.y) / an.w / 0.1f;
                float tw = __logf(g.z / an.z) / 0.2f;
                float th = __logf(g.w / an.w) / 0.2f;
                float4 bp = ((const float4*)box)[(size_t)b*NAA + a];
                float d0=bp.x-tx, d1=bp.y-ty, d2=bp.z-tw, d3=bp.w-th;
                float e0=fabsf(d0), e1=fabsf(d1), e2=fabsf(d2), e3=fabsf(d3);
                l_rg = ((e0<1.f)?0.5f*d0*d0:e0-0.5f) + ((e1<1.f)?0.5f*d1*d1:e1-0.5f)
                     + ((e2<1.f)?0.5f*d2*d2:e2-0.5f) + ((e3<1.f)?0.5f*d3*d3:e3-0.5f);
                g_negbits[row] = SENT;
            } else if (ign){
                g_negbits[row] = SENT;
            } else {
                float ce = fmaxf(lse - r[0], 0.f);
                unsigned bits = __float_as_uint(ce);
                g_negbits[row] = bits;
                atomicAdd(&g_hcnt[b*NBIN + (bits>>18)], 1u);
                atomicAdd(&g_hsum[b*NBIN + (bits>>18)], ce);
            }
        }
        // reduce the 8 group leaders of each warp into lane 0
        #pragma unroll
        for (int off=4; off<32; off<<=1){
            l_np += __shfl_xor_sync(0xFFFFFFFFu, l_np, off);
            l_ce += __shfl_xor_sync(0xFFFFFFFFu, l_ce, off);
            l_rg += __shfl_xor_sync(0xFFFFFFFFu, l_rg, off);
        }
        if ((t&31)==0 && l_np > 0.f){
            int b = (cur*TILE + rloc) >> 15;
            atomicAdd(&g_numpos[b], l_np);
            atomicAdd(&g_posce[b],  l_ce);
            atomicAdd(&g_regsum[b], l_rg);
        }
        if (nxt >= NTILES) break;
        cur = nxt; idx ^= 1;
    }
}

// ---------------- warp-scale select over 512 smem bins -------------------------
__device__ void warp_select(const unsigned* cnt, const float* fs, int K,
                            int* o_bin, int* o_k, float* o_S){
    int l = threadIdx.x;               // caller guarantees l < 32
    int base = l*16;
    unsigned c=0; float f=0.f;
    #pragma unroll
    for (int j=0;j<16;++j){ c+=cnt[base+j]; f+=fs[base+j]; }
    unsigned ci=c; float fi=f;
    #pragma unroll
    for (int off=1;off<32;off<<=1){
        unsigned uc=__shfl_up_sync(0xFFFFFFFFu,ci,off);
        float    uf=__shfl_up_sync(0xFFFFFFFFu,fi,off);
        if (l>=off){ ci+=uc; fi+=uf; }
    }
    unsigned total=__shfl_sync(0xFFFFFFFFu,ci,31);
    float    ftot =__shfl_sync(0xFFFFFFFFu,fi,31);
    unsigned SA=total-ci; float FA=ftot-fi;
    if (SA < (unsigned)K && (unsigned)K <= SA + c){
        unsigned run=SA; float fab=FA;
        for (int j=15;j>=0;--j){
            unsigned cb=cnt[base+j];
            if (run + cb >= (unsigned)K){ *o_bin=base+j; *o_k=(int)((unsigned)K-run); *o_S=fab; break; }
            run += cb; fab += fs[base+j];
        }
    }
}

// ---------------- K3: exact top-K, ~1 global pass ------------------------------
__global__ void __launch_bounds__(1024) k_select(){
    int b=blockIdx.x&31, sel=blockIdx.x>>5, t=threadIdx.x;
    int lane=t&31, warp=t>>5;
    const unsigned* cnt=g_hcnt + b*NBIN;
    const float*    fsm=g_hsum + b*NBIN;
    __shared__ unsigned swc[32]; __shared__ float swf[32];
    __shared__ int s_t1, s_k1;  __shared__ float s_S1;
    __shared__ int s_bin, s_k;  __shared__ float s_S;
    __shared__ int s_n;
    __shared__ unsigned cnt2[512]; __shared__ float fs2[512];
    __shared__ unsigned slist[CAP];

    int base=t*16;
    unsigned c=0; float f=0.f;
    #pragma unroll
    for (int j=0;j<16;++j){ c+=cnt[base+j]; f+=fsm[base+j]; }
    unsigned ci=c; float fi=f;
    #pragma unroll
    for (int off=1;off<32;off<<=1){
        unsigned uc=__shfl_up_sync(0xFFFFFFFFu,ci,off);
        float    uf=__shfl_up_sync(0xFFFFFFFFu,fi,off);
        if (lane>=off){ ci+=uc; fi+=uf; }
    }
    if (lane==31){ swc[warp]=ci; swf[warp]=fi; }
    __syncthreads();
    if (t<32){
        unsigned u=swc[t]; float g=swf[t];
        #pragma unroll
        for (int off=1;off<32;off<<=1){
            unsigned uu=__shfl_up_sync(0xFFFFFFFFu,u,off);
            float    gg=__shfl_up_sync(0xFFFFFFFFu,g,off);
            if (t>=off){ u+=uu; g+=gg; }
        }
        swc[t]=u; swf[t]=g;
    }
    __syncthreads();
    unsigned P = ci + (warp ? swc[warp-1] : 0u);
    float    FP= fi + (warp ? swf[warp-1] : 0.f);
    unsigned total=swc[31]; float ftot=swf[31];

    float np = g_numpos[b];
    int negcnt = (int)total;
    int K = sel ? min(100, negcnt) : min(3*(int)np, negcnt);
    if (t==0) g_K[blockIdx.x] = K;
    if (K<=0){ if (t==0) g_topk[blockIdx.x]=0.f; return; }

    unsigned SA = total - P; float FA = ftot - FP;
    if (SA < (unsigned)K && (unsigned)K <= SA + c){
        unsigned run=SA; float fab=FA;
        for (int j=15;j>=0;--j){
            unsigned cb=cnt[base+j];
            if (run + cb >= (unsigned)K){ s_t1=base+j; s_k1=(int)((unsigned)K-run); s_S1=fab; break; }
            run += cb; fab += fsm[base+j];
        }
    }
    if (t==0) s_n=0;
    for (int i=t;i<512;i+=1024){ cnt2[i]=0u; fs2[i]=0.f; }
    __syncthreads();
    int t1=s_t1, k1=s_k1; float S1=s_S1;
    unsigned cT1 = cnt[t1];
    const unsigned* vals = g_negbits + b*NAA;
    bool collect = (cT1 <= CAP);
    if (collect){
        for (int i=t;i<NAA;i+=1024){
            unsigned v=vals[i];
            if ((v>>18)==(unsigned)t1){ int p=atomicAdd(&s_n,1); slist[p]=v; }
        }
    }
    __syncthreads();
    int n=s_n;
    if (collect){
        for (int i=t;i<n;i+=1024){
            unsigned v=slist[i];
            atomicAdd(&cnt2[(v>>9)&511u],1u); atomicAdd(&fs2[(v>>9)&511u],__uint_as_float(v));
        }
    } else {
        for (int i=t;i<NAA;i+=1024){
            unsigned v=vals[i];
            if ((v>>18)==(unsigned)t1){ atomicAdd(&cnt2[(v>>9)&511u],1u); atomicAdd(&fs2[(v>>9)&511u],__uint_as_float(v)); }
        }
    }
    __syncthreads();
    if (t<32) warp_select(cnt2, fs2, k1, &s_bin, &s_k, &s_S);
    __syncthreads();
    int t2=s_bin, k2=s_k; float S2=s_S;
    for (int i=t;i<512;i+=1024){ cnt2[i]=0u; fs2[i]=0.f; }
    __syncthreads();
    unsigned pfx = ((unsigned)t1<<9) | (unsigned)t2;
    if (collect){
        for (int i=t;i<n;i+=1024){
            unsigned v=slist[i];
            if ((v>>9)==pfx){ atomicAdd(&cnt2[v&511u],1u); atomicAdd(&fs2[v&511u],__uint_as_float(v)); }
        }
    } else {
        for (int i=t;i<NAA;i+=1024){
            unsigned v=vals[i];
            if ((v>>9)==pfx){ atomicAdd(&cnt2[v&511u],1u); atomicAdd(&fs2[v&511u],__uint_as_float(v)); }
        }
    }
    __syncthreads();
    if (t<32) warp_select(cnt2, fs2, k2, &s_bin, &s_k, &s_S);
    __syncthreads();
    if (t==0){
        unsigned tv = (pfx<<9) | (unsigned)s_bin;
        g_topk[blockIdx.x] = S1 + S2 + s_S + (float)s_k * __uint_as_float(tv);
    }
}

// ---------------- K4: deterministic final reduce -------------------------------
__global__ void k_final(float* __restrict__ out){
    if (threadIdx.x==0){
        float cs=0.f, rs=0.f, ns=0.f;
        for (int b=0;b<BB;++b){
            float np=g_numpos[b]; int npos=(int)np;
            int K=g_K[b], K0=g_K[32+b];
            float cls_pos  = (K>0)  ? (g_posce[b]+g_topk[b]) / fmaxf(np+(float)K,1.f)
                                    : g_posce[b] / fmaxf(np,1.f);
            float cls_zero = (K0>0) ? g_topk[32+b] / fmaxf((float)K0,1.f) : 0.f;
            cs += (npos>0) ? cls_pos : cls_zero;
            rs += (npos>0) ? g_regsum[b] / fmaxf(np*4.f,1.f) : 0.f;
            ns += np;
        }
        out[0]=cs/(float)BB; out[1]=rs/(float)BB; out[2]=ns/(float)BB;
    }
}

// ---------------- launch -------------------------------------------------------
extern "C" void kernel_launch(void* const* d_in, const int* in_sizes, int n_in,
                              void* d_out, int out_size) {
    const float* cls=nullptr; const float* box=nullptr; const float* anc=nullptr;
    const float* gtb=nullptr; const int* gtl=nullptr;
    for (int i=0;i<n_in;++i){
        long sz=in_sizes[i];
        if      (sz==(long)BB*NAA*CC) cls=(const float*)d_in[i];
        else if (sz==(long)BB*NAA*4)  box=(const float*)d_in[i];
        else if (sz==(long)NAA*4)     anc=(const float*)d_in[i];
        else if (sz==(long)BB*NGG*4)  gtb=(const float*)d_in[i];
        else if (sz==(long)BB*NGG)    gtl=(const int*)d_in[i];
    }
    const int smem = 2*TILE*CC*4;   // 165888 B
    cudaFuncSetAttribute(k_main, cudaFuncAttributeMaxDynamicSharedMemorySize, smem);
    k_init<<<512,256>>>();
    k_iou<<<dim3(NAA/1024, BB), 256>>>(anc, gtb);
    k_force<<<1, BB*NGG>>>();
    k_main<<<160, MTH, smem>>>(cls, box, anc, gtb, gtl);
    k_select<<<64, 1024>>>();
    k_final<<<1, 32>>>((float*)d_out);
}

// round 5
// speedup vs baseline: 1.1774x; 1.1774x over previous
#include <cuda_runtime.h>
#include <cuda_pipeline.h>
#include <cstdint>
#include <cstddef>

#define BB   32
#define NAA  32768
#define CC   81
#define NGG  24
#define SENT 0xFFFFFFFFu
#define NBIN 16384
#define TILE 128
#define NTILES ((BB*NAA)/TILE)      // 8192
#define TILE_F4 ((TILE*CC)/4)       // 2592
#define CAP  6144
#define MGRID 296                   // 2 blocks/SM

// ---------------- scratch ------------------------------------------------------
__device__ float              g_ioumax[BB*NAA];
__device__ unsigned char      g_gtidx[BB*NAA];
__device__ unsigned long long g_bestkey[BB*NGG];
__device__ unsigned           g_negbits[BB*NAA];
__device__ unsigned           g_hcnt[BB*NBIN];
__device__ float              g_hsum[BB*NBIN];
__device__ float              g_numpos[BB], g_posce[BB], g_regsum[BB];
__device__ float              g_topk[2*BB];
__device__ int                g_K[2*BB];
__device__ int                g_ctr;

__device__ __forceinline__ unsigned redux_max(unsigned v){
    unsigned r; asm("redux.sync.max.u32 %0, %1, 0xffffffff;" : "=r"(r) : "r"(v)); return r;
}

// ---------------- init ---------------------------------------------------------
__global__ void k_init(){
    int i = blockIdx.x*256 + threadIdx.x;
    for (int j=i; j<BB*NBIN; j+=gridDim.x*256){ g_hcnt[j]=0u; g_hsum[j]=0.f; }
    if (i < BB*NGG) g_bestkey[i]=0ull;
    if (i < BB){ g_numpos[i]=0.f; g_posce[i]=0.f; g_regsum[i]=0.f; }
    if (i==0) g_ctr = 0;
}

// ---------------- K1: IoU matching (4 anchors/thread, REDUX per-GT) ------------
__global__ void __launch_bounds__(256) k_iou(const float* __restrict__ anchors,
                                             const float* __restrict__ gtb){
    __shared__ float gx0[NGG],gy0[NGG],gx1[NGG],gy1[NGG],garea[NGG];
    __shared__ unsigned long long skey[NGG];
    int b=blockIdx.y, t=threadIdx.x;
    if (t<NGG){
        float4 g=((const float4*)gtb)[b*NGG+t];
        float x0=g.x-0.5f*g.z, y0=g.y-0.5f*g.w, x1=g.x+0.5f*g.z, y1=g.y+0.5f*g.w;
        gx0[t]=x0; gy0[t]=y0; gx1[t]=x1; gy1[t]=y1; garea[t]=(x1-x0)*(y1-y0);
        skey[t]=0ull;
    }
    __syncthreads();
    int abase = blockIdx.x*1024 + t;
    float ax0[4],ay0[4],ax1[4],ay1[4],areaA[4];
    #pragma unroll
    for (int k=0;k<4;++k){
        float4 an=((const float4*)anchors)[abase+k*256];
        ax0[k]=an.x-0.5f*an.z; ay0[k]=an.y-0.5f*an.w;
        ax1[k]=an.x+0.5f*an.z; ay1[k]=an.y+0.5f*an.w;
        areaA[k]=(ax1[k]-ax0[k])*(ay1[k]-ay0[k]);
    }
    float best[4]={-1.f,-1.f,-1.f,-1.f}; int bg[4]={0,0,0,0};

    for (int g=0; g<NGG; ++g){
        float bi=-1.f; int bk=0;
        #pragma unroll
        for (int k=0;k<4;++k){
            float lx=fmaxf(ax0[k],gx0[g]), ly=fmaxf(ay0[k],gy0[g]);
            float rx=fminf(ax1[k],gx1[g]), ry=fminf(ay1[k],gy1[g]);
            float w=fmaxf(rx-lx,0.f), h=fmaxf(ry-ly,0.f);
            float inter=w*h;
            float uni=fmaxf(areaA[k]+garea[g]-inter, 1e-12f);
            float iou=inter/uni;
            if (iou>best[k]){best[k]=iou; bg[k]=g;}
            if (iou>bi){bi=iou; bk=k;}
        }
        unsigned mb=__float_as_uint(bi);
        unsigned M=redux_max(mb);
        unsigned rk=(mb==M)? (unsigned)(((3-bk)<<5)|(31-(t&31)))+1u : 0u;
        unsigned R=redux_max(rk);
        if ((t&31)==0){
            int wl=31-(int)((R-1u)&31u), wk=3-(int)((R-1u)>>5);
            unsigned a=(unsigned)(blockIdx.x*1024 + (t&~31) + wl + wk*256);
            atomicMax(&skey[g], ((unsigned long long)M<<32) | (0xFFFFFFFFu - a));
        }
    }
    #pragma unroll
    for (int k=0;k<4;++k){
        g_ioumax[b*NAA+abase+k*256]=best[k];
        g_gtidx[b*NAA+abase+k*256]=(unsigned char)bg[k];
    }
    __syncthreads();
    if (t<NGG) atomicMax(&g_bestkey[b*NGG+t], skey[t]);
}

// ---------------- K1b: mark forced positives (iou := 2.0) ----------------------
__global__ void k_force(){
    int i = threadIdx.x;
    if (i < BB*NGG){
        unsigned a = 0xFFFFFFFFu - (unsigned)(g_bestkey[i] & 0xFFFFFFFFull);
        int b = i / NGG;
        g_ioumax[(size_t)b*NAA + a] = 2.0f;
    }
}

// ---------------- K2: CE + classify + reg; 2 lanes/row, 2 blocks/SM ------------
__global__ void __launch_bounds__(256,2) k_main(const float* __restrict__ cls,
                                                const float* __restrict__ box,
                                                const float* __restrict__ anchors,
                                                const float* __restrict__ gtb,
                                                const int*   __restrict__ gtl){
    extern __shared__ float sbuf[];
    const int t = threadIdx.x;
    float* bufs[2] = { sbuf, sbuf + TILE*CC };
    __shared__ int s_next;
    const int rloc = t >> 1;       // row within tile
    const int j    = t & 1;        // lane within pair

    if (t==0) s_next = atomicAdd(&g_ctr, 1);
    __syncthreads();
    int cur = s_next;
    if (cur >= NTILES) return;
    {   // tile cur -> buf0
        const float4* src=(const float4*)(cls + (size_t)cur*TILE*CC);
        float4* dst=(float4*)bufs[0];
        for (int i=t;i<TILE_F4;i+=256) __pipeline_memcpy_async(dst+i, src+i, 16);
    }
    __pipeline_commit();
    if (t==0) s_next = atomicAdd(&g_ctr, 1);
    __syncthreads();
    int nxt = s_next;
    if (nxt < NTILES){
        const float4* src=(const float4*)(cls + (size_t)nxt*TILE*CC);
        float4* dst=(float4*)bufs[1];
        for (int i=t;i<TILE_F4;i+=256) __pipeline_memcpy_async(dst+i, src+i, 16);
    }
    __pipeline_commit();

    int idx = 0;
    for(;;){
        __pipeline_wait_prior(1);          // tile `cur` staged (empty groups finish instantly)
        __syncthreads();
        if (t==0 && nxt < NTILES) s_next = atomicAdd(&g_ctr, 1);   // overlap with compute

        int row = cur*TILE + rloc;
        int b   = row >> 15;
        int a   = row & (NAA-1);
        // leader-side early loads (latency hidden under exp loop)
        float io = 0.f; int gi = 0;
        if (j==0){ io = g_ioumax[row]; gi = (int)g_gtidx[row]; }

        const float* r = bufs[idx] + rloc*CC;
        float s0=0.f,s1=0.f,s2=0.f,s3=0.f;
        #pragma unroll
        for (int c=0;c<80;c+=8){
            s0 += __expf(r[c+j]);
            s1 += __expf(r[c+2+j]);
            s2 += __expf(r[c+4+j]);
            s3 += __expf(r[c+6+j]);
        }
        float s = (s0+s1)+(s2+s3);
        if (j==0) s += __expf(r[80]);
        s += __shfl_xor_sync(0xFFFFFFFFu, s, 1);

        float l_np=0.f, l_ce=0.f, l_rg=0.f;
        if (j==0){
            float lse = __logf(s);
            bool pos = io >= 0.5f;             // forced positives carry io=2.0
            bool ign = (!pos) && (io > 0.4f);
            if (pos){
                int tgt = gtl[b*NGG + gi];
                float ce = fmaxf(lse - r[tgt], 0.f);
                l_np = 1.f; l_ce = ce;
                float4 an = ((const float4*)anchors)[a];
                float4 g  = ((const float4*)gtb)[b*NGG + gi];
                float tx = (g.x - an.x) / an.z / 0.1f;
                float ty = (g.y - an.y) / an.w / 0.1f;
                float tw = __logf(g.z / an.z) / 0.2f;
                float th = __logf(g.w / an.w) / 0.2f;
                float4 bp = ((const float4*)box)[(size_t)b*NAA + a];
                float d0=bp.x-tx, d1=bp.y-ty, d2=bp.z-tw, d3=bp.w-th;
                float e0=fabsf(d0), e1=fabsf(d1), e2=fabsf(d2), e3=fabsf(d3);
                l_rg = ((e0<1.f)?0.5f*d0*d0:e0-0.5f) + ((e1<1.f)?0.5f*d1*d1:e1-0.5f)
                     + ((e2<1.f)?0.5f*d2*d2:e2-0.5f) + ((e3<1.f)?0.5f*d3*d3:e3-0.5f);
                g_negbits[row] = SENT;
            } else if (ign){
                g_negbits[row] = SENT;
            } else {
                float ce = fmaxf(lse - r[0], 0.f);
                unsigned bits = __float_as_uint(ce);
                g_negbits[row] = bits;
                atomicAdd(&g_hcnt[b*NBIN + (bits>>18)], 1u);
                atomicAdd(&g_hsum[b*NBIN + (bits>>18)], ce);
            }
        }
        // reduce 16 even-lane leaders into lane 0
        #pragma unroll
        for (int off=2; off<32; off<<=1){
            l_np += __shfl_xor_sync(0xFFFFFFFFu, l_np, off);
            l_ce += __shfl_xor_sync(0xFFFFFFFFu, l_ce, off);
            l_rg += __shfl_xor_sync(0xFFFFFFFFu, l_rg, off);
        }
        if ((t&31)==0 && l_np > 0.f){
            atomicAdd(&g_numpos[b], l_np);
            atomicAdd(&g_posce[b],  l_ce);
            atomicAdd(&g_regsum[b], l_rg);
        }

        __syncthreads();                   // buf[idx] free; s_next visible
        if (nxt >= NTILES) break;
        int n2 = s_next;
        if (n2 < NTILES){
            const float4* src=(const float4*)(cls + (size_t)n2*TILE*CC);
            float4* dst=(float4*)bufs[idx];
            for (int i=t;i<TILE_F4;i+=256) __pipeline_memcpy_async(dst+i, src+i, 16);
        }
        __pipeline_commit();
        cur = nxt; nxt = n2; idx ^= 1;
    }
}

// ---------------- warp-scale select over 512 smem bins -------------------------
__device__ void warp_select(const unsigned* cnt, const float* fs, int K,
                            int* o_bin, int* o_k, float* o_S){
    int l = threadIdx.x;               // caller guarantees l < 32
    int base = l*16;
    unsigned c=0; float f=0.f;
    #pragma unroll
    for (int j=0;j<16;++j){ c+=cnt[base+j]; f+=fs[base+j]; }
    unsigned ci=c; float fi=f;
    #pragma unroll
    for (int off=1;off<32;off<<=1){
        unsigned uc=__shfl_up_sync(0xFFFFFFFFu,ci,off);
        float    uf=__shfl_up_sync(0xFFFFFFFFu,fi,off);
        if (l>=off){ ci+=uc; fi+=uf; }
    }
    unsigned total=__shfl_sync(0xFFFFFFFFu,ci,31);
    float    ftot =__shfl_sync(0xFFFFFFFFu,fi,31);
    unsigned SA=total-ci; float FA=ftot-fi;
    if (SA < (unsigned)K && (unsigned)K <= SA + c){
        unsigned run=SA; float fab=FA;
        for (int j=15;j>=0;--j){
            unsigned cb=cnt[base+j];
            if (run + cb >= (unsigned)K){ *o_bin=base+j; *o_k=(int)((unsigned)K-run); *o_S=fab; break; }
            run += cb; fab += fs[base+j];
        }
    }
}

// ---------------- K3: exact top-K, ~1 global pass ------------------------------
__global__ void __launch_bounds__(1024) k_select(){
    int b=blockIdx.x&31, sel=blockIdx.x>>5, t=threadIdx.x;
    int lane=t&31, warp=t>>5;
    const unsigned* cnt=g_hcnt + b*NBIN;
    const float*    fsm=g_hsum + b*NBIN;
    __shared__ unsigned swc[32]; __shared__ float swf[32];
    __shared__ int s_t1, s_k1;  __shared__ float s_S1;
    __shared__ int s_bin, s_k;  __shared__ float s_S;
    __shared__ int s_n;
    __shared__ unsigned cnt2[512]; __shared__ float fs2[512];
    __shared__ unsigned slist[CAP];

    int base=t*16;
    unsigned c=0; float f=0.f;
    #pragma unroll
    for (int j=0;j<16;++j){ c+=cnt[base+j]; f+=fsm[base+j]; }
    unsigned ci=c; float fi=f;
    #pragma unroll
    for (int off=1;off<32;off<<=1){
        unsigned uc=__shfl_up_sync(0xFFFFFFFFu,ci,off);
        float    uf=__shfl_up_sync(0xFFFFFFFFu,fi,off);
        if (lane>=off){ ci+=uc; fi+=uf; }
    }
    if (lane==31){ swc[warp]=ci; swf[warp]=fi; }
    __syncthreads();
    if (t<32){
        unsigned u=swc[t]; float g=swf[t];
        #pragma unroll
        for (int off=1;off<32;off<<=1){
            unsigned uu=__shfl_up_sync(0xFFFFFFFFu,u,off);
            float    gg=__shfl_up_sync(0xFFFFFFFFu,g,off);
            if (t>=off){ u+=uu; g+=gg; }
        }
        swc[t]=u; swf[t]=g;
    }
    __syncthreads();
    unsigned P = ci + (warp ? swc[warp-1] : 0u);
    float    FP= fi + (warp ? swf[warp-1] : 0.f);
    unsigned total=swc[31]; float ftot=swf[31];

    float np = g_numpos[b];
    int negcnt = (int)total;
    int K = sel ? min(100, negcnt) : min(3*(int)np, negcnt);
    if (t==0) g_K[blockIdx.x] = K;
    if (K<=0){ if (t==0) g_topk[blockIdx.x]=0.f; return; }

    unsigned SA = total - P; float FA = ftot - FP;
    if (SA < (unsigned)K && (unsigned)K <= SA + c){
        unsigned run=SA; float fab=FA;
        for (int j=15;j>=0;--j){
            unsigned cb=cnt[base+j];
            if (run + cb >= (unsigned)K){ s_t1=base+j; s_k1=(int)((unsigned)K-run); s_S1=fab; break; }
            run += cb; fab += fsm[base+j];
        }
    }
    if (t==0) s_n=0;
    for (int i=t;i<512;i+=1024){ cnt2[i]=0u; fs2[i]=0.f; }
    __syncthreads();
    int t1=s_t1, k1=s_k1; float S1=s_S1;
    unsigned cT1 = cnt[t1];
    const unsigned* vals = g_negbits + b*NAA;
    bool collect = (cT1 <= CAP);
    if (collect){
        for (int i=t;i<NAA;i+=1024){
            unsigned v=vals[i];
            if ((v>>18)==(unsigned)t1){ int p=atomicAdd(&s_n,1); slist[p]=v; }
        }
    }
    __syncthreads();
    int n=s_n;
    if (collect){
        for (int i=t;i<n;i+=1024){
            unsigned v=slist[i];
            atomicAdd(&cnt2[(v>>9)&511u],1u); atomicAdd(&fs2[(v>>9)&511u],__uint_as_float(v));
        }
    } else {
        for (int i=t;i<NAA;i+=1024){
            unsigned v=vals[i];
            if ((v>>18)==(unsigned)t1){ atomicAdd(&cnt2[(v>>9)&511u],1u); atomicAdd(&fs2[(v>>9)&511u],__uint_as_float(v)); }
        }
    }
    __syncthreads();
    if (t<32) warp_select(cnt2, fs2, k1, &s_bin, &s_k, &s_S);
    __syncthreads();
    int t2=s_bin, k2=s_k; float S2=s_S;
    for (int i=t;i<512;i+=1024){ cnt2[i]=0u; fs2[i]=0.f; }
    __syncthreads();
    unsigned pfx = ((unsigned)t1<<9) | (unsigned)t2;
    if (collect){
        for (int i=t;i<n;i+=1024){
            unsigned v=slist[i];
            if ((v>>9)==pfx){ atomicAdd(&cnt2[v&511u],1u); atomicAdd(&fs2[v&511u],__uint_as_float(v)); }
        }
    } else {
        for (int i=t;i<NAA;i+=1024){
            unsigned v=vals[i];
            if ((v>>9)==pfx){ atomicAdd(&cnt2[v&511u],1u); atomicAdd(&fs2[v&511u],__uint_as_float(v)); }
        }
    }
    __syncthreads();
    if (t<32) warp_select(cnt2, fs2, k2, &s_bin, &s_k, &s_S);
    __syncthreads();
    if (t==0){
        unsigned tv = (pfx<<9) | (unsigned)s_bin;
        g_topk[blockIdx.x] = S1 + S2 + s_S + (float)s_k * __uint_as_float(tv);
    }
}

// ---------------- K4: deterministic final reduce -------------------------------
__global__ void k_final(float* __restrict__ out){
    if (threadIdx.x==0){
        float cs=0.f, rs=0.f, ns=0.f;
        for (int b=0;b<BB;++b){
            float np=g_numpos[b]; int npos=(int)np;
            int K=g_K[b], K0=g_K[32+b];
            float cls_pos  = (K>0)  ? (g_posce[b]+g_topk[b]) / fmaxf(np+(float)K,1.f)
                                    : g_posce[b] / fmaxf(np,1.f);
            float cls_zero = (K0>0) ? g_topk[32+b] / fmaxf((float)K0,1.f) : 0.f;
            cs += (npos>0) ? cls_pos : cls_zero;
            rs += (npos>0) ? g_regsum[b] / fmaxf(np*4.f,1.f) : 0.f;
            ns += np;
        }
        out[0]=cs/(float)BB; out[1]=rs/(float)BB; out[2]=ns/(float)BB;
    }
}

// ---------------- launch -------------------------------------------------------
extern "C" void kernel_launch(void* const* d_in, const int* in_sizes, int n_in,
                              void* d_out, int out_size) {
    const float* cls=nullptr; const float* box=nullptr; const float* anc=nullptr;
    const float* gtb=nullptr; const int* gtl=nullptr;
    for (int i=0;i<n_in;++i){
        long sz=in_sizes[i];
        if      (sz==(long)BB*NAA*CC) cls=(const float*)d_in[i];
        else if (sz==(long)BB*NAA*4)  box=(const float*)d_in[i];
        else if (sz==(long)NAA*4)     anc=(const float*)d_in[i];
        else if (sz==(long)BB*NGG*4)  gtb=(const float*)d_in[i];
        else if (sz==(long)BB*NGG)    gtl=(const int*)d_in[i];
    }
    const int smem = 2*TILE*CC*4;   // 82944 B -> 2 blocks/SM
    cudaFuncSetAttribute(k_main, cudaFuncAttributeMaxDynamicSharedMemorySize, smem);
    k_init<<<512,256>>>();
    k_iou<<<dim3(NAA/1024, BB), 256>>>(anc, gtb);
    k_force<<<1, BB*NGG>>>();
    k_main<<<MGRID, 256, smem>>>(cls, box, anc, gtb, gtl);
    k_select<<<64, 1024>>>();
    k_final<<<1, 32>>>((float*)d_out);
}

// round 6
// speedup vs baseline: 1.3578x; 1.1532x over previous
#include <cuda_runtime.h>
#include <cstdint>
#include <cstddef>

#define BB    32
#define NAA   32768
#define CC    81
#define NGG   24
#define SENT  0xFFFFFFFFu
#define NBIN  16384
#define CAP   6144
#define NPAIRS (BB*NAA/2)          // 524288
#define MBLK  888                  // 6 blocks/SM * 148
#define NWRP  (MBLK*8)             // 7104 warps
#define CHUNK ((NPAIRS + NWRP - 1)/NWRP)   // 74 pairs per warp

// ---------------- scratch ------------------------------------------------------
__device__ unsigned char      g_meta[BB*NAA];     // bit7 pos, bit6 ign, bits0-5 gi
__device__ unsigned long long g_bestkey[BB*NGG];
__device__ unsigned           g_negbits[BB*NAA];
__device__ unsigned           g_hcnt[BB*NBIN];
__device__ float              g_hsum[BB*NBIN];
__device__ float              g_numpos[BB], g_posce[BB], g_regsum[BB];
__device__ float              g_topk[2*BB];
__device__ int                g_K[2*BB];

__device__ __forceinline__ unsigned redux_max(unsigned v){
    unsigned r; asm("redux.sync.max.u32 %0, %1, 0xffffffff;" : "=r"(r) : "r"(v)); return r;
}

// ---------------- init ---------------------------------------------------------
__global__ void k_init(){
    int i = blockIdx.x*256 + threadIdx.x;
    for (int j=i; j<BB*NBIN; j+=gridDim.x*256){ g_hcnt[j]=0u; g_hsum[j]=0.f; }
    if (i < BB*NGG) g_bestkey[i]=0ull;
    if (i < BB){ g_numpos[i]=0.f; g_posce[i]=0.f; g_regsum[i]=0.f; }
}

// ---------------- K1: IoU matching (4 anchors/thread, refined-rcp iou) ---------
__global__ void __launch_bounds__(256) k_iou(const float* __restrict__ anchors,
                                             const float* __restrict__ gtb){
    __shared__ float gx0[NGG],gy0[NGG],gx1[NGG],gy1[NGG],garea[NGG];
    __shared__ unsigned long long skey[NGG];
    int b=blockIdx.y, t=threadIdx.x;
    if (t<NGG){
        float4 g=((const float4*)gtb)[b*NGG+t];
        float x0=g.x-0.5f*g.z, y0=g.y-0.5f*g.w, x1=g.x+0.5f*g.z, y1=g.y+0.5f*g.w;
        gx0[t]=x0; gy0[t]=y0; gx1[t]=x1; gy1[t]=y1; garea[t]=(x1-x0)*(y1-y0);
        skey[t]=0ull;
    }
    __syncthreads();
    int abase = blockIdx.x*1024 + t;
    float ax0[4],ay0[4],ax1[4],ay1[4],areaA[4];
    #pragma unroll
    for (int k=0;k<4;++k){
        float4 an=((const float4*)anchors)[abase+k*256];
        ax0[k]=an.x-0.5f*an.z; ay0[k]=an.y-0.5f*an.w;
        ax1[k]=an.x+0.5f*an.z; ay1[k]=an.y+0.5f*an.w;
        areaA[k]=(ax1[k]-ax0[k])*(ay1[k]-ay0[k]);
    }
    float best[4]={-1.f,-1.f,-1.f,-1.f}; int bg[4]={0,0,0,0};

    for (int g=0; g<NGG; ++g){
        float bi=-1.f; int bk=0;
        #pragma unroll
        for (int k=0;k<4;++k){
            float lx=fmaxf(ax0[k],gx0[g]), ly=fmaxf(ay0[k],gy0[g]);
            float rx=fminf(ax1[k],gx1[g]), ry=fminf(ay1[k],gy1[g]);
            float w=fmaxf(rx-lx,0.f), h=fmaxf(ry-ly,0.f);
            float inter=w*h;
            float uni=fmaxf(areaA[k]+garea[g]-inter, 1e-12f);
            float rcp; asm("rcp.approx.ftz.f32 %0, %1;" : "=f"(rcp) : "f"(uni));
            rcp = rcp * __fmaf_rn(-uni, rcp, 2.0f);     // Newton -> ~1ulp of div.rn
            float iou = inter * rcp;
            if (iou>best[k]){best[k]=iou; bg[k]=g;}
            if (iou>bi){bi=iou; bk=k;}
        }
        unsigned mb=__float_as_uint(bi);
        unsigned M=redux_max(mb);
        unsigned rk=(mb==M)? (unsigned)(((3-bk)<<5)|(31-(t&31)))+1u : 0u;
        unsigned R=redux_max(rk);
        if ((t&31)==0){
            int wl=31-(int)((R-1u)&31u), wk=3-(int)((R-1u)>>5);
            unsigned a=(unsigned)(blockIdx.x*1024 + (t&~31) + wl + wk*256);
            atomicMax(&skey[g], ((unsigned long long)M<<32) | (0xFFFFFFFFu - a));
        }
    }
    #pragma unroll
    for (int k=0;k<4;++k){
        bool pos = best[k] >= 0.5f;
        bool ign = (!pos) && (best[k] > 0.4f);
        unsigned char mB = (unsigned char)(bg[k] | (pos?0x80:(ign?0x40:0)));
        g_meta[b*NAA + abase + k*256] = mB;
    }
    __syncthreads();
    if (t<NGG) atomicMax(&g_bestkey[b*NGG+t], skey[t]);
}

// ---------------- K1b: mark forced positives -----------------------------------
__global__ void k_force(){
    int i = threadIdx.x;
    if (i < BB*NGG){
        unsigned a = 0xFFFFFFFFu - (unsigned)(g_bestkey[i] & 0xFFFFFFFFull);
        int b = i / NGG;
        size_t idx = (size_t)b*NAA + a;
        g_meta[idx] = (unsigned char)(g_meta[idx] | 0x80);  // benign dup race
    }
}

// ---------------- K2: CE + classify + reg; direct global, warp per 2 rows ------
__global__ void __launch_bounds__(256,6) k_main(const float* __restrict__ cls,
                                                const float* __restrict__ box,
                                                const float* __restrict__ anchors,
                                                const float* __restrict__ gtb,
                                                const int*   __restrict__ gtl){
    const int lane = threadIdx.x & 31;
    const int W = blockIdx.x*8 + (threadIdx.x>>5);
    int pbeg = W*CHUNK;
    int pend = min(pbeg + CHUNK, NPAIRS);
    if (pbeg >= pend) return;

    float l_np=0.f, l_ce=0.f, l_rg=0.f;
    int bcur = pbeg >> 14;

    for (int p = pbeg; p < pend; ++p){
        int b = p >> 14;
        if (b != bcur){
            if (l_np != 0.f){
                atomicAdd(&g_numpos[bcur], l_np);
                atomicAdd(&g_posce[bcur],  l_ce);
                atomicAdd(&g_regsum[bcur], l_rg);
                l_np=0.f; l_ce=0.f; l_rg=0.f;
            }
            bcur = b;
        }
        unsigned mm = reinterpret_cast<const unsigned short*>(g_meta)[p];
        const float* r0 = cls + (size_t)p*162;
        float v00 = r0[lane],    v01 = r0[lane+32];
        float v10 = r0[81+lane], v11 = r0[81+lane+32];
        float v02 = 0.f, v12 = 0.f;
        if (lane < 17){ v02 = r0[lane+64]; v12 = r0[81+lane+64]; }

        float s0 = __expf(v00) + __expf(v01);
        float s1 = __expf(v10) + __expf(v11);
        if (lane < 17){ s0 += __expf(v02); s1 += __expf(v12); }
        #pragma unroll
        for (int off=16; off; off>>=1){
            s0 += __shfl_xor_sync(0xFFFFFFFFu, s0, off);
            s1 += __shfl_xor_sync(0xFFFFFFFFu, s1, off);
        }
        float lse0 = __logf(s0), lse1 = __logf(s1);
        float r00 = __shfl_sync(0xFFFFFFFFu, v00, 0);
        float r10 = __shfl_sync(0xFFFFFFFFu, v10, 0);

        bool pos0 = (mm & 0x80u)   != 0, ign0 = (mm & 0x40u)   != 0;
        bool pos1 = (mm & 0x8000u) != 0, ign1 = (mm & 0x4000u) != 0;
        int row0 = 2*p, row1 = row0 + 1;

        if (lane == 0){
            if (pos0 | ign0) g_negbits[row0] = SENT;
            else {
                float ce = fmaxf(lse0 - r00, 0.f);
                unsigned bits = __float_as_uint(ce);
                g_negbits[row0] = bits;
                atomicAdd(&g_hcnt[b*NBIN + (bits>>18)], 1u);
                atomicAdd(&g_hsum[b*NBIN + (bits>>18)], ce);
            }
        }
        if (lane == 1){
            if (pos1 | ign1) g_negbits[row1] = SENT;
            else {
                float ce = fmaxf(lse1 - r10, 0.f);
                unsigned bits = __float_as_uint(ce);
                g_negbits[row1] = bits;
                atomicAdd(&g_hcnt[b*NBIN + (bits>>18)], 1u);
                atomicAdd(&g_hsum[b*NBIN + (bits>>18)], ce);
            }
        }
        if (pos0){                                   // warp-uniform, rare
            int gi = mm & 0x3F;
            int tgt = gtl[b*NGG + gi];
            int slot = tgt >> 5;
            float val = (slot==0)?v00:((slot==1)?v01:v02);
            float vt = __shfl_sync(0xFFFFFFFFu, val, tgt & 31);
            if (lane == 0){
                int a = row0 & (NAA-1);
                l_np += 1.f;
                l_ce += fmaxf(lse0 - vt, 0.f);
                float4 an = ((const float4*)anchors)[a];
                float4 g  = ((const float4*)gtb)[b*NGG + gi];
                float tx = (g.x - an.x) / an.z / 0.1f;
                float ty = (g.y - an.y) / an.w / 0.1f;
                float tw = __logf(g.z / an.z) / 0.2f;
                float th = __logf(g.w / an.w) / 0.2f;
                float4 bp = ((const float4*)box)[(size_t)b*NAA + a];
                float d0=bp.x-tx, d1=bp.y-ty, d2=bp.z-tw, d3=bp.w-th;
                float e0=fabsf(d0), e1=fabsf(d1), e2=fabsf(d2), e3=fabsf(d3);
                l_rg += ((e0<1.f)?0.5f*d0*d0:e0-0.5f) + ((e1<1.f)?0.5f*d1*d1:e1-0.5f)
                      + ((e2<1.f)?0.5f*d2*d2:e2-0.5f) + ((e3<1.f)?0.5f*d3*d3:e3-0.5f);
            }
        }
        if (pos1){                                   // warp-uniform, rare
            int gi = (mm >> 8) & 0x3F;
            int tgt = gtl[b*NGG + gi];
            int slot = tgt >> 5;
            float val = (slot==0)?v10:((slot==1)?v11:v12);
            float vt = __shfl_sync(0xFFFFFFFFu, val, tgt & 31);
            if (lane == 1){
                int a = row1 & (NAA-1);
                l_np += 1.f;
                l_ce += fmaxf(lse1 - vt, 0.f);
                float4 an = ((const float4*)anchors)[a];
                float4 g  = ((const float4*)gtb)[b*NGG + gi];
                float tx = (g.x - an.x) / an.z / 0.1f;
                float ty = (g.y - an.y) / an.w / 0.1f;
                float tw = __logf(g.z / an.z) / 0.2f;
                float th = __logf(g.w / an.w) / 0.2f;
                float4 bp = ((const float4*)box)[(size_t)b*NAA + a];
                float d0=bp.x-tx, d1=bp.y-ty, d2=bp.z-tw, d3=bp.w-th;
                float e0=fabsf(d0), e1=fabsf(d1), e2=fabsf(d2), e3=fabsf(d3);
                l_rg += ((e0<1.f)?0.5f*d0*d0:e0-0.5f) + ((e1<1.f)?0.5f*d1*d1:e1-0.5f)
                      + ((e2<1.f)?0.5f*d2*d2:e2-0.5f) + ((e3<1.f)?0.5f*d3*d3:e3-0.5f);
            }
        }
    }
    if (l_np != 0.f){
        atomicAdd(&g_numpos[bcur], l_np);
        atomicAdd(&g_posce[bcur],  l_ce);
        atomicAdd(&g_regsum[bcur], l_rg);
    }
}

// ---------------- warp-scale select over 512 smem bins -------------------------
__device__ void warp_select(const unsigned* cnt, const float* fs, int K,
                            int* o_bin, int* o_k, float* o_S){
    int l = threadIdx.x;
    int base = l*16;
    unsigned c=0; float f=0.f;
    #pragma unroll
    for (int j=0;j<16;++j){ c+=cnt[base+j]; f+=fs[base+j]; }
    unsigned ci=c; float fi=f;
    #pragma unroll
    for (int off=1;off<32;off<<=1){
        unsigned uc=__shfl_up_sync(0xFFFFFFFFu,ci,off);
        float    uf=__shfl_up_sync(0xFFFFFFFFu,fi,off);
        if (l>=off){ ci+=uc; fi+=uf; }
    }
    unsigned total=__shfl_sync(0xFFFFFFFFu,ci,31);
    float    ftot =__shfl_sync(0xFFFFFFFFu,fi,31);
    unsigned SA=total-ci; float FA=ftot-fi;
    if (SA < (unsigned)K && (unsigned)K <= SA + c){
        unsigned run=SA; float fab=FA;
        for (int j=15;j>=0;--j){
            unsigned cb=cnt[base+j];
            if (run + cb >= (unsigned)K){ *o_bin=base+j; *o_k=(int)((unsigned)K-run); *o_S=fab; break; }
            run += cb; fab += fs[base+j];
        }
    }
}

// ---------------- K3: exact top-K ----------------------------------------------
__global__ void __launch_bounds__(1024) k_select(){
    int b=blockIdx.x&31, sel=blockIdx.x>>5, t=threadIdx.x;
    int lane=t&31, warp=t>>5;
    const unsigned* cnt=g_hcnt + b*NBIN;
    const float*    fsm=g_hsum + b*NBIN;
    __shared__ unsigned swc[32]; __shared__ float swf[32];
    __shared__ int s_t1, s_k1;  __shared__ float s_S1;
    __shared__ int s_bin, s_k;  __shared__ float s_S;
    __shared__ int s_n;
    __shared__ unsigned cnt2[512]; __shared__ float fs2[512];
    __shared__ unsigned slist[CAP];

    int base=t*16;
    unsigned c=0; float f=0.f;
    #pragma unroll
    for (int j=0;j<16;++j){ c+=cnt[base+j]; f+=fsm[base+j]; }
    unsigned ci=c; float fi=f;
    #pragma unroll
    for (int off=1;off<32;off<<=1){
        unsigned uc=__shfl_up_sync(0xFFFFFFFFu,ci,off);
        float    uf=__shfl_up_sync(0xFFFFFFFFu,fi,off);
        if (lane>=off){ ci+=uc; fi+=uf; }
    }
    if (lane==31){ swc[warp]=ci; swf[warp]=fi; }
    __syncthreads();
    if (t<32){
        unsigned u=swc[t]; float g=swf[t];
        #pragma unroll
        for (int off=1;off<32;off<<=1){
            unsigned uu=__shfl_up_sync(0xFFFFFFFFu,u,off);
            float    gg=__shfl_up_sync(0xFFFFFFFFu,g,off);
            if (t>=off){ u+=uu; g+=gg; }
        }
        swc[t]=u; swf[t]=g;
    }
    __syncthreads();
    unsigned P = ci + (warp ? swc[warp-1] : 0u);
    float    FP= fi + (warp ? swf[warp-1] : 0.f);
    unsigned total=swc[31]; float ftot=swf[31];

    float np = g_numpos[b];
    int negcnt = (int)total;
    int K = sel ? min(100, negcnt) : min(3*(int)np, negcnt);
    if (t==0) g_K[blockIdx.x] = K;
    if (K<=0){ if (t==0) g_topk[blockIdx.x]=0.f; return; }

    unsigned SA = total - P; float FA = ftot - FP;
    if (SA < (unsigned)K && (unsigned)K <= SA + c){
        unsigned run=SA; float fab=FA;
        for (int j=15;j>=0;--j){
            unsigned cb=cnt[base+j];
            if (run + cb >= (unsigned)K){ s_t1=base+j; s_k1=(int)((unsigned)K-run); s_S1=fab; break; }
            run += cb; fab += fsm[base+j];
        }
    }
    if (t==0) s_n=0;
    for (int i=t;i<512;i+=1024){ cnt2[i]=0u; fs2[i]=0.f; }
    __syncthreads();
    int t1=s_t1, k1=s_k1; float S1=s_S1;
    unsigned cT1 = cnt[t1];
    const unsigned* vals = g_negbits + b*NAA;
    bool collect = (cT1 <= CAP);
    if (collect){
        for (int i=t;i<NAA;i+=1024){
            unsigned v=vals[i];
            if ((v>>18)==(unsigned)t1){ int p=atomicAdd(&s_n,1); slist[p]=v; }
        }
    }
    __syncthreads();
    int n=s_n;
    if (collect){
        for (int i=t;i<n;i+=1024){
            unsigned v=slist[i];
            atomicAdd(&cnt2[(v>>9)&511u],1u); atomicAdd(&fs2[(v>>9)&511u],__uint_as_float(v));
        }
    } else {
        for (int i=t;i<NAA;i+=1024){
            unsigned v=vals[i];
            if ((v>>18)==(unsigned)t1){ atomicAdd(&cnt2[(v>>9)&511u],1u); atomicAdd(&fs2[(v>>9)&511u],__uint_as_float(v)); }
        }
    }
    __syncthreads();
    if (t<32) warp_select(cnt2, fs2, k1, &s_bin, &s_k, &s_S);
    __syncthreads();
    int t2=s_bin, k2=s_k; float S2=s_S;
    for (int i=t;i<512;i+=1024){ cnt2[i]=0u; fs2[i]=0.f; }
    __syncthreads();
    unsigned pfx = ((unsigned)t1<<9) | (unsigned)t2;
    if (collect){
        for (int i=t;i<n;i+=1024){
            unsigned v=slist[i];
            if ((v>>9)==pfx){ atomicAdd(&cnt2[v&511u],1u); atomicAdd(&fs2[v&511u],__uint_as_float(v)); }
        }
    } else {
        for (int i=t;i<NAA;i+=1024){
            unsigned v=vals[i];
            if ((v>>9)==pfx){ atomicAdd(&cnt2[v&511u],1u); atomicAdd(&fs2[v&511u],__uint_as_float(v)); }
        }
    }
    __syncthreads();
    if (t<32) warp_select(cnt2, fs2, k2, &s_bin, &s_k, &s_S);
    __syncthreads();
    if (t==0){
        unsigned tv = (pfx<<9) | (unsigned)s_bin;
        g_topk[blockIdx.x] = S1 + S2 + s_S + (float)s_k * __uint_as_float(tv);
    }
}

// ---------------- K4: deterministic final reduce -------------------------------
__global__ void k_final(float* __restrict__ out){
    if (threadIdx.x==0){
        float cs=0.f, rs=0.f, ns=0.f;
        for (int b=0;b<BB;++b){
            float np=g_numpos[b]; int npos=(int)np;
            int K=g_K[b], K0=g_K[32+b];
            float cls_pos  = (K>0)  ? (g_posce[b]+g_topk[b]) / fmaxf(np+(float)K,1.f)
                                    : g_posce[b] / fmaxf(np,1.f);
            float cls_zero = (K0>0) ? g_topk[32+b] / fmaxf((float)K0,1.f) : 0.f;
            cs += (npos>0) ? cls_pos : cls_zero;
            rs += (npos>0) ? g_regsum[b] / fmaxf(np*4.f,1.f) : 0.f;
            ns += np;
        }
        out[0]=cs/(float)BB; out[1]=rs/(float)BB; out[2]=ns/(float)BB;
    }
}

// ---------------- launch -------------------------------------------------------
extern "C" void kernel_launch(void* const* d_in, const int* in_sizes, int n_in,
                              void* d_out, int out_size) {
    const float* cls=nullptr; const float* box=nullptr; const float* anc=nullptr;
    const float* gtb=nullptr; const int* gtl=nullptr;
    for (int i=0;i<n_in;++i){
        long sz=in_sizes[i];
        if      (sz==(long)BB*NAA*CC) cls=(const float*)d_in[i];
        else if (sz==(long)BB*NAA*4)  box=(const float*)d_in[i];
        else if (sz==(long)NAA*4)     anc=(const float*)d_in[i];
        else if (sz==(long)BB*NGG*4)  gtb=(const float*)d_in[i];
        else if (sz==(long)BB*NGG)    gtl=(const int*)d_in[i];
    }
    k_init<<<512,256>>>();
    k_iou<<<dim3(NAA/1024, BB), 256>>>(anc, gtb);
    k_force<<<1, BB*NGG>>>();
    k_main<<<MBLK, 256>>>(cls, box, anc, gtb, gtl);
    k_select<<<64, 1024>>>();
    k_final<<<1, 32>>>((float*)d_out);
}

// round 7
// speedup vs baseline: 1.4304x; 1.0535x over previous
#include <cuda_runtime.h>
#include <cstdint>
#include <cstddef>

#define BB    32
#define NAA   32768
#define CC    81
#define NGG   24
#define SENT  0xFFFFFFFFu
#define NBIN  16384
#define CAP   6144
#define NPAIRS (BB*NAA/2)          // 524288
#define MBLK  888                  // 6 blocks/SM * 148
#define NWRP  (MBLK*8)             // 7104 warps
#define CHUNK ((NPAIRS + NWRP - 1)/NWRP)   // 74 pairs per warp

// ---------------- scratch ------------------------------------------------------
__device__ unsigned char      g_meta[BB*NAA];     // bit7 pos, bit6 ign, bits0-5 gi
__device__ unsigned long long g_bestkey[BB*NGG];
__device__ unsigned           g_negbits[BB*NAA];
__device__ unsigned           g_hcnt[BB*NBIN];
__device__ float              g_hsum[BB*NBIN];
__device__ float              g_numpos[BB], g_posce[BB], g_regsum[BB];
__device__ float              g_topk[2*BB];
__device__ int                g_K[2*BB];

__device__ __forceinline__ unsigned redux_max(unsigned v){
    unsigned r; asm("redux.sync.max.u32 %0, %1, 0xffffffff;" : "=r"(r) : "r"(v)); return r;
}

// ---------------- init ---------------------------------------------------------
__global__ void k_init(){
    int i = blockIdx.x*256 + threadIdx.x;
    for (int j=i; j<BB*NBIN; j+=gridDim.x*256){ g_hcnt[j]=0u; g_hsum[j]=0.f; }
    if (i < BB*NGG) g_bestkey[i]=0ull;
    if (i < BB){ g_numpos[i]=0.f; g_posce[i]=0.f; g_regsum[i]=0.f; }
}

// ---------------- K1: IoU matching (4 anchors/thread, refined-rcp iou) ---------
__global__ void __launch_bounds__(256) k_iou(const float* __restrict__ anchors,
                                             const float* __restrict__ gtb){
    __shared__ float gx0[NGG],gy0[NGG],gx1[NGG],gy1[NGG],garea[NGG];
    __shared__ unsigned long long skey[NGG];
    int b=blockIdx.y, t=threadIdx.x;
    if (t<NGG){
        float4 g=((const float4*)gtb)[b*NGG+t];
        float x0=g.x-0.5f*g.z, y0=g.y-0.5f*g.w, x1=g.x+0.5f*g.z, y1=g.y+0.5f*g.w;
        gx0[t]=x0; gy0[t]=y0; gx1[t]=x1; gy1[t]=y1; garea[t]=(x1-x0)*(y1-y0);
        skey[t]=0ull;
    }
    __syncthreads();
    int abase = blockIdx.x*1024 + t;
    float ax0[4],ay0[4],ax1[4],ay1[4],areaA[4];
    #pragma unroll
    for (int k=0;k<4;++k){
        float4 an=((const float4*)anchors)[abase+k*256];
        ax0[k]=an.x-0.5f*an.z; ay0[k]=an.y-0.5f*an.w;
        ax1[k]=an.x+0.5f*an.z; ay1[k]=an.y+0.5f*an.w;
        areaA[k]=(ax1[k]-ax0[k])*(ay1[k]-ay0[k]);
    }
    float best[4]={-1.f,-1.f,-1.f,-1.f}; int bg[4]={0,0,0,0};

    for (int g=0; g<NGG; ++g){
        float bi=-1.f; int bk=0;
        #pragma unroll
        for (int k=0;k<4;++k){
            float lx=fmaxf(ax0[k],gx0[g]), ly=fmaxf(ay0[k],gy0[g]);
            float rx=fminf(ax1[k],gx1[g]), ry=fminf(ay1[k],gy1[g]);
            float w=fmaxf(rx-lx,0.f), h=fmaxf(ry-ly,0.f);
            float inter=w*h;
            float uni=fmaxf(areaA[k]+garea[g]-inter, 1e-12f);
            float rcp; asm("rcp.approx.ftz.f32 %0, %1;" : "=f"(rcp) : "f"(uni));
            rcp = rcp * __fmaf_rn(-uni, rcp, 2.0f);     // Newton -> ~1ulp of div.rn
            float iou = inter * rcp;
            if (iou>best[k]){best[k]=iou; bg[k]=g;}
            if (iou>bi){bi=iou; bk=k;}
        }
        unsigned mb=__float_as_uint(bi);
        unsigned M=redux_max(mb);
        unsigned rk=(mb==M)? (unsigned)(((3-bk)<<5)|(31-(t&31)))+1u : 0u;
        unsigned R=redux_max(rk);
        if ((t&31)==0){
            int wl=31-(int)((R-1u)&31u), wk=3-(int)((R-1u)>>5);
            unsigned a=(unsigned)(blockIdx.x*1024 + (t&~31) + wl + wk*256);
            atomicMax(&skey[g], ((unsigned long long)M<<32) | (0xFFFFFFFFu - a));
        }
    }
    #pragma unroll
    for (int k=0;k<4;++k){
        bool pos = best[k] >= 0.5f;
        bool ign = (!pos) && (best[k] > 0.4f);
        unsigned char mB = (unsigned char)(bg[k] | (pos?0x80:(ign?0x40:0)));
        g_meta[b*NAA + abase + k*256] = mB;
    }
    __syncthreads();
    if (t<NGG) atomicMax(&g_bestkey[b*NGG+t], skey[t]);
}

// ---------------- K1b: mark forced positives -----------------------------------
__global__ void k_force(){
    int i = threadIdx.x;
    if (i < BB*NGG){
        unsigned a = 0xFFFFFFFFu - (unsigned)(g_bestkey[i] & 0xFFFFFFFFull);
        int b = i / NGG;
        size_t idx = (size_t)b*NAA + a;
        g_meta[idx] = (unsigned char)(g_meta[idx] | 0x80);  // benign dup race
    }
}

// ---------------- K2: CE + classify + reg; half-warp per row -------------------
__global__ void __launch_bounds__(256,6) k_main(const float* __restrict__ cls,
                                                const float* __restrict__ box,
                                                const float* __restrict__ anchors,
                                                const float* __restrict__ gtb,
                                                const int*   __restrict__ gtl){
    const int lane = threadIdx.x & 31;
    const int l16  = lane & 15;
    const int h    = lane >> 4;
    const unsigned leader = (unsigned)(h << 4);
    const int W = blockIdx.x*8 + (threadIdx.x>>5);
    int pbeg = W*CHUNK;
    int pend = min(pbeg + CHUNK, NPAIRS);
    if (pbeg >= pend) return;

    float l_np=0.f, l_ce=0.f, l_rg=0.f;
    int bcur = pbeg >> 14;
    const float* rp = cls + (size_t)pbeg*162 + h*81 + l16;

    for (int p = pbeg; p < pend; ++p, rp += 162){
        int b = p >> 14;
        if (b != bcur){
            if (__any_sync(0xFFFFFFFFu, l_np != 0.f)){
                float a0=l_np, c0=l_ce, r0=l_rg;
                a0 += __shfl_down_sync(0xFFFFFFFFu, a0, 16);
                c0 += __shfl_down_sync(0xFFFFFFFFu, c0, 16);
                r0 += __shfl_down_sync(0xFFFFFFFFu, r0, 16);
                if (lane==0){
                    atomicAdd(&g_numpos[bcur], a0);
                    atomicAdd(&g_posce[bcur],  c0);
                    atomicAdd(&g_regsum[bcur], r0);
                }
                l_np=0.f; l_ce=0.f; l_rg=0.f;
            }
            bcur = b;
        }
        unsigned mm = reinterpret_cast<const unsigned short*>(g_meta)[p];
        float v0 = rp[0],  v1 = rp[16], v2 = rp[32], v3 = rp[48], v4 = rp[64];
        float v5 = (l16==0) ? rp[80] : 0.f;

        float s = __expf(v0) + __expf(v1) + __expf(v2) + __expf(v3) + __expf(v4);
        if (l16==0) s += __expf(v5);
        s += __shfl_xor_sync(0xFFFFFFFFu, s, 1);
        s += __shfl_xor_sync(0xFFFFFFFFu, s, 2);
        s += __shfl_xor_sync(0xFFFFFFFFu, s, 4);
        s += __shfl_xor_sync(0xFFFFFFFFu, s, 8);
        float lse = __logf(s);

        unsigned mb = (mm >> (h*8)) & 0xFFu;
        bool pos = (mb & 0x80u) != 0;
        bool ign = (mb & 0x40u) != 0;

        if (l16==0){
            int rowh = 2*p + h;
            if (pos | ign) g_negbits[rowh] = SENT;
            else {
                float ce = fmaxf(lse - v0, 0.f);        // v0 = row[0] on leader
                unsigned bits = __float_as_uint(ce);
                g_negbits[rowh] = bits;
                atomicAdd(&g_hcnt[b*NBIN + (bits>>18)], 1u);
                atomicAdd(&g_hsum[b*NBIN + (bits>>18)], ce);
            }
        }
        if (__any_sync(0xFFFFFFFFu, pos)){               // rare, warp-uniform branch
            int gi = (int)(mb & 0x3Fu);
            int tl = 0;
            if (l16==0 && pos) tl = gtl[b*NGG + gi];
            int tgt = __shfl_sync(0xFFFFFFFFu, tl, leader);
            int slot = tgt >> 4;
            float val = (slot==0)?v0:(slot==1)?v1:(slot==2)?v2:(slot==3)?v3:(slot==4)?v4:v5;
            float vt = __shfl_sync(0xFFFFFFFFu, val, (unsigned)((tgt&15))|leader);
            if (l16==0 && pos){
                int a = (2*p + h) & (NAA-1);
                l_np += 1.f;
                l_ce += fmaxf(lse - vt, 0.f);
                float4 an = ((const float4*)anchors)[a];
                float4 g  = ((const float4*)gtb)[b*NGG + gi];
                float tx = (g.x - an.x) / an.z / 0.1f;
                float ty = (g.y - an.y) / an.w / 0.1f;
                float tw = __logf(g.z / an.z) / 0.2f;
                float th = __logf(g.w / an.w) / 0.2f;
                float4 bp = ((const float4*)box)[(size_t)b*NAA + a];
                float d0=bp.x-tx, d1=bp.y-ty, d2=bp.z-tw, d3=bp.w-th;
                float e0=fabsf(d0), e1=fabsf(d1), e2=fabsf(d2), e3=fabsf(d3);
                l_rg += ((e0<1.f)?0.5f*d0*d0:e0-0.5f) + ((e1<1.f)?0.5f*d1*d1:e1-0.5f)
                      + ((e2<1.f)?0.5f*d2*d2:e2-0.5f) + ((e3<1.f)?0.5f*d3*d3:e3-0.5f);
            }
        }
    }
    if (__any_sync(0xFFFFFFFFu, l_np != 0.f)){
        float a0=l_np, c0=l_ce, r0=l_rg;
        a0 += __shfl_down_sync(0xFFFFFFFFu, a0, 16);
        c0 += __shfl_down_sync(0xFFFFFFFFu, c0, 16);
        r0 += __shfl_down_sync(0xFFFFFFFFu, r0, 16);
        if (lane==0){
            atomicAdd(&g_numpos[bcur], a0);
            atomicAdd(&g_posce[bcur],  c0);
            atomicAdd(&g_regsum[bcur], r0);
        }
    }
}

// ---------------- warp-scale select over 512 smem bins -------------------------
__device__ void warp_select(const unsigned* cnt, const float* fs, int K,
                            int* o_bin, int* o_k, float* o_S){
    int l = threadIdx.x;
    int base = l*16;
    unsigned c=0; float f=0.f;
    #pragma unroll
    for (int j=0;j<16;++j){ c+=cnt[base+j]; f+=fs[base+j]; }
    unsigned ci=c; float fi=f;
    #pragma unroll
    for (int off=1;off<32;off<<=1){
        unsigned uc=__shfl_up_sync(0xFFFFFFFFu,ci,off);
        float    uf=__shfl_up_sync(0xFFFFFFFFu,fi,off);
        if (l>=off){ ci+=uc; fi+=uf; }
    }
    unsigned total=__shfl_sync(0xFFFFFFFFu,ci,31);
    float    ftot =__shfl_sync(0xFFFFFFFFu,fi,31);
    unsigned SA=total-ci; float FA=ftot-fi;
    if (SA < (unsigned)K && (unsigned)K <= SA + c){
        unsigned run=SA; float fab=FA;
        for (int j=15;j>=0;--j){
            unsigned cb=cnt[base+j];
            if (run + cb >= (unsigned)K){ *o_bin=base+j; *o_k=(int)((unsigned)K-run); *o_S=fab; break; }
            run += cb; fab += fs[base+j];
        }
    }
}

// ---------------- K3: exact top-K ----------------------------------------------
__global__ void __launch_bounds__(1024) k_select(){
    int b=blockIdx.x&31, sel=blockIdx.x>>5, t=threadIdx.x;
    int lane=t&31, warp=t>>5;
    const unsigned* cnt=g_hcnt + b*NBIN;
    const float*    fsm=g_hsum + b*NBIN;
    __shared__ unsigned swc[32]; __shared__ float swf[32];
    __shared__ int s_t1, s_k1;  __shared__ float s_S1;
    __shared__ int s_bin, s_k;  __shared__ float s_S;
    __shared__ int s_n;
    __shared__ unsigned cnt2[512]; __shared__ float fs2[512];
    __shared__ unsigned slist[CAP];

    int base=t*16;
    unsigned c=0; float f=0.f;
    #pragma unroll
    for (int j=0;j<16;++j){ c+=cnt[base+j]; f+=fsm[base+j]; }
    unsigned ci=c; float fi=f;
    #pragma unroll
    for (int off=1;off<32;off<<=1){
        unsigned uc=__shfl_up_sync(0xFFFFFFFFu,ci,off);
        float    uf=__shfl_up_sync(0xFFFFFFFFu,fi,off);
        if (lane>=off){ ci+=uc; fi+=uf; }
    }
    if (lane==31){ swc[warp]=ci; swf[warp]=fi; }
    __syncthreads();
    if (t<32){
        unsigned u=swc[t]; float g=swf[t];
        #pragma unroll
        for (int off=1;off<32;off<<=1){
            unsigned uu=__shfl_up_sync(0xFFFFFFFFu,u,off);
            float    gg=__shfl_up_sync(0xFFFFFFFFu,g,off);
            if (t>=off){ u+=uu; g+=gg; }
        }
        swc[t]=u; swf[t]=g;
    }
    __syncthreads();
    unsigned P = ci + (warp ? swc[warp-1] : 0u);
    float    FP= fi + (warp ? swf[warp-1] : 0.f);
    unsigned total=swc[31]; float ftot=swf[31];

    float np = g_numpos[b];
    int negcnt = (int)total;
    int K = sel ? min(100, negcnt) : min(3*(int)np, negcnt);
    if (t==0) g_K[blockIdx.x] = K;
    if (K<=0){ if (t==0) g_topk[blockIdx.x]=0.f; return; }

    unsigned SA = total - P; float FA = ftot - FP;
    if (SA < (unsigned)K && (unsigned)K <= SA + c){
        unsigned run=SA; float fab=FA;
        for (int j=15;j>=0;--j){
            unsigned cb=cnt[base+j];
            if (run + cb >= (unsigned)K){ s_t1=base+j; s_k1=(int)((unsigned)K-run); s_S1=fab; break; }
            run += cb; fab += fsm[base+j];
        }
    }
    if (t==0) s_n=0;
    for (int i=t;i<512;i+=1024){ cnt2[i]=0u; fs2[i]=0.f; }
    __syncthreads();
    int t1=s_t1, k1=s_k1; float S1=s_S1;
    unsigned cT1 = cnt[t1];
    const unsigned* vals = g_negbits + b*NAA;
    bool collect = (cT1 <= CAP);
    if (collect){
        for (int i=t;i<NAA;i+=1024){
            unsigned v=vals[i];
            if ((v>>18)==(unsigned)t1){ int p=atomicAdd(&s_n,1); slist[p]=v; }
        }
    }
    __syncthreads();
    int n=s_n;
    if (collect){
        for (int i=t;i<n;i+=1024){
            unsigned v=slist[i];
            atomicAdd(&cnt2[(v>>9)&511u],1u); atomicAdd(&fs2[(v>>9)&511u],__uint_as_float(v));
        }
    } else {
        for (int i=t;i<NAA;i+=1024){
            unsigned v=vals[i];
            if ((v>>18)==(unsigned)t1){ atomicAdd(&cnt2[(v>>9)&511u],1u); atomicAdd(&fs2[(v>>9)&511u],__uint_as_float(v)); }
        }
    }
    __syncthreads();
    if (t<32) warp_select(cnt2, fs2, k1, &s_bin, &s_k, &s_S);
    __syncthreads();
    int t2=s_bin, k2=s_k; float S2=s_S;
    for (int i=t;i<512;i+=1024){ cnt2[i]=0u; fs2[i]=0.f; }
    __syncthreads();
    unsigned pfx = ((unsigned)t1<<9) | (unsigned)t2;
    if (collect){
        for (int i=t;i<n;i+=1024){
            unsigned v=slist[i];
            if ((v>>9)==pfx){ atomicAdd(&cnt2[v&511u],1u); atomicAdd(&fs2[v&511u],__uint_as_float(v)); }
        }
    } else {
        for (int i=t;i<NAA;i+=1024){
            unsigned v=vals[i];
            if ((v>>9)==pfx){ atomicAdd(&cnt2[v&511u],1u); atomicAdd(&fs2[v&511u],__uint_as_float(v)); }
        }
    }
    __syncthreads();
    if (t<32) warp_select(cnt2, fs2, k2, &s_bin, &s_k, &s_S);
    __syncthreads();
    if (t==0){
        unsigned tv = (pfx<<9) | (unsigned)s_bin;
        g_topk[blockIdx.x] = S1 + S2 + s_S + (float)s_k * __uint_as_float(tv);
    }
}

// ---------------- K4: deterministic final reduce -------------------------------
__global__ void k_final(float* __restrict__ out){
    if (threadIdx.x==0){
        float cs=0.f, rs=0.f, ns=0.f;
        for (int b=0;b<BB;++b){
            float np=g_numpos[b]; int npos=(int)np;
            int K=g_K[b], K0=g_K[32+b];
            float cls_pos  = (K>0)  ? (g_posce[b]+g_topk[b]) / fmaxf(np+(float)K,1.f)
                                    : g_posce[b] / fmaxf(np,1.f);
            float cls_zero = (K0>0) ? g_topk[32+b] / fmaxf((float)K0,1.f) : 0.f;
            cs += (npos>0) ? cls_pos : cls_zero;
            rs += (npos>0) ? g_regsum[b] / fmaxf(np*4.f,1.f) : 0.f;
            ns += np;
        }
        out[0]=cs/(float)BB; out[1]=rs/(float)BB; out[2]=ns/(float)BB;
    }
}

// ---------------- launch -------------------------------------------------------
extern "C" void kernel_launch(void* const* d_in, const int* in_sizes, int n_in,
                              void* d_out, int out_size) {
    const float* cls=nullptr; const float* box=nullptr; const float* anc=nullptr;
    const float* gtb=nullptr; const int* gtl=nullptr;
    for (int i=0;i<n_in;++i){
        long sz=in_sizes[i];
        if      (sz==(long)BB*NAA*CC) cls=(const float*)d_in[i];
        else if (sz==(long)BB*NAA*4)  box=(const float*)d_in[i];
        else if (sz==(long)NAA*4)     anc=(const float*)d_in[i];
        else if (sz==(long)BB*NGG*4)  gtb=(const float*)d_in[i];
        else if (sz==(long)BB*NGG)    gtl=(const int*)d_in[i];
    }
    k_init<<<512,256>>>();
    k_iou<<<dim3(NAA/1024, BB), 256>>>(anc, gtb);
    k_force<<<1, BB*NGG>>>();
    k_main<<<MBLK, 256>>>(cls, box, anc, gtb, gtl);
    k_select<<<64, 1024>>>();
    k_final<<<1, 32>>>((float*)d_out);
}